// round 12
// baseline (speedup 1.0000x reference)
#include <cuda_runtime.h>
#include <cuda_bf16.h>

#define NN 100000
#define FF 64
#define HH 8
#define DD 8
#define EE 1200000
#define HID 32

// scratch (allocation-free rule: __device__ globals)
__device__ float g_src_buf[NN * FF];        // fp32 (pull path)
__device__ float g_dst_buf[NN * FF];        // fp32 (node-att path)
__device__ unsigned g_src_bf[NN * FF / 2];  // bf16x2 rows (MLP gather path)
__device__ unsigned g_dst_bf[NN * FF / 2];
__device__ float att_buf[(size_t)EE * HH];  // per-edge attention (fp32)
__device__ int deg_buf[NN];
__device__ int off_buf[NN + 1];
__device__ int cur_buf[NN];
__device__ int2 rec_buf[EE];                // (src, eid) grouped by dst
__device__ int g_idx_is64;

__device__ __forceinline__ float leaky(float x) { return fmaxf(x, 0.2f * x); }
__device__ __forceinline__ float sigm(float x) { return 1.0f / (1.0f + __expf(-x)); }

__device__ __forceinline__ unsigned pack_bf16(float lo, float hi) {
    __nv_bfloat162 t = __float22bfloat162_rn(make_float2(lo, hi));
    return *(unsigned*)&t;
}

__device__ __forceinline__ float2 unpack_bf16(unsigned u) {
    __nv_bfloat162 t = *(__nv_bfloat162*)&u;
    return __bfloat1622float2(t);
}

// split x into bf16 hi + bf16 lo (residual)
__device__ __forceinline__ void split_pack(float a, float b, unsigned& hi, unsigned& lo) {
    __nv_bfloat16 ah = __float2bfloat16(a), bh = __float2bfloat16(b);
    float ar = a - __bfloat162float(ah);
    float br = b - __bfloat162float(bh);
    __nv_bfloat162 t; t.x = ah; t.y = bh;
    hi = *(unsigned*)&t;
    lo = pack_bf16(ar, br);
}

// D += A@B, m16n8k16, bf16 in / fp32 accum
__device__ __forceinline__ void mma16816(float* d, const unsigned* a, const unsigned* b) {
    asm volatile(
        "mma.sync.aligned.m16n8k16.row.col.f32.bf16.bf16.f32 "
        "{%0,%1,%2,%3}, {%4,%5,%6,%7}, {%8,%9}, {%0,%1,%2,%3};"
        : "+f"(d[0]), "+f"(d[1]), "+f"(d[2]), "+f"(d[3])
        : "r"(a[0]), "r"(a[1]), "r"(a[2]), "r"(a[3]), "r"(b[0]), "r"(b[1]));
}

#define LMW32 36               // staging row stride in uint32 (72 bf16), conflict-free
#define ATTS 10                // att row stride (node kernel only)

// ---------------------------------------------------------------------------
// CSR build pass 1: zero histogram + probe edge_index dtype.
__global__ void zero_kernel(const unsigned int* __restrict__ eidx_words) {
    int n = blockIdx.x * 256 + threadIdx.x;
    if (n < NN) deg_buf[n] = 0;
    if (blockIdx.x == 0 && threadIdx.x == 0) {
        int is64 = 1;
        for (int i = 0; i < 8; i++)
            if (eidx_words[2 * i + 1] != 0u) is64 = 0;
        g_idx_is64 = is64;
    }
}

// CSR build pass 2: histogram of dst.
__global__ void hist_kernel(const void* __restrict__ edge_index) {
    int e = blockIdx.x * 256 + threadIdx.x;
    if (e >= EE) return;
    int d;
    if (g_idx_is64) d = (int)((const long long*)edge_index)[EE + e];
    else            d = ((const int*)edge_index)[EE + e];
    atomicAdd(&deg_buf[d], 1);
}

// CSR build pass 3: exclusive scan (single block, 1024 threads).
__global__ __launch_bounds__(1024) void scan_kernel() {
    __shared__ int partial[1024];
    const int t = threadIdx.x;
    const int CH = (NN + 1023) / 1024;   // 98
    const int base = t * CH;

    int sum = 0;
    for (int i = 0; i < CH; i++) {
        int idx = base + i;
        if (idx < NN) sum += deg_buf[idx];
    }
    partial[t] = sum;
    __syncthreads();

    // Hillis-Steele inclusive scan
    for (int s = 1; s < 1024; s <<= 1) {
        int v = partial[t];
        int o = (t >= s) ? partial[t - s] : 0;
        __syncthreads();
        partial[t] = v + o;
        __syncthreads();
    }

    int run = (t > 0) ? partial[t - 1] : 0;
    for (int i = 0; i < CH; i++) {
        int idx = base + i;
        if (idx < NN) {
            off_buf[idx] = run;
            cur_buf[idx] = run;
            run += deg_buf[idx];
        }
    }
    if (t == 1023) off_buf[NN] = run;   // = EE
}

// CSR build pass 4: fill records grouped by dst.
__global__ void fill_kernel(const void* __restrict__ edge_index) {
    int e = blockIdx.x * 256 + threadIdx.x;
    if (e >= EE) return;
    int s, d;
    if (g_idx_is64) {
        const long long* ei = (const long long*)edge_index;
        s = (int)ei[e]; d = (int)ei[EE + e];
    } else {
        const int* ei = (const int*)edge_index;
        s = ei[e]; d = ei[EE + e];
    }
    int pos = atomicAdd(&cur_buf[d], 1);
    rec_buf[pos] = make_int2(s, e);
}

// ---------------------------------------------------------------------------
// Fused node kernel (unchanged): tensor-core GEMM (hi/lo split) + node
// attention + bf16 mirror stores.
__global__ __launch_bounds__(128) void node_kernel(
    const float* __restrict__ h,
    const float* __restrict__ W_src, const float* __restrict__ b_src,
    const float* __restrict__ W_dst, const float* __restrict__ b_dst,
    const float* __restrict__ Wa1, const float* __restrict__ ba1,
    const float* __restrict__ Wa2, const float* __restrict__ ba2,
    float* __restrict__ out)
{
    __shared__ unsigned AHI[128 * LMW32];
    __shared__ unsigned ALO[128 * LMW32];
    __shared__ float ATT[4][32 * ATTS];

    const int tid  = threadIdx.x;
    const int warp = tid >> 5;
    const int lane = tid & 31;
    const int c = lane & 3;
    const int r = lane >> 2;
    const int blockbase = blockIdx.x * 128;

    const int mat = warp >> 1;
    const int colbase = 32 * (warp & 1);
    const float* Wm = mat ? W_dst : W_src;
    const float* bm = mat ? b_dst : b_src;

    unsigned bhi[4][4][2], blo[4][4][2];
    #pragma unroll
    for (int ks = 0; ks < 4; ks++)
        #pragma unroll
        for (int nt = 0; nt < 4; nt++) {
            const float* base = Wm + (16 * ks + 2 * c) * FF + colbase + 8 * nt + r;
            split_pack(base[0],       base[FF],     bhi[ks][nt][0], blo[ks][nt][0]);
            split_pack(base[8 * FF],  base[9 * FF], bhi[ks][nt][1], blo[ks][nt][1]);
        }
    float gb0[4], gb1[4];
    #pragma unroll
    for (int nt = 0; nt < 4; nt++) {
        gb0[nt] = bm[colbase + 8 * nt + 2 * c];
        gb1[nt] = bm[colbase + 8 * nt + 2 * c + 1];
    }

    unsigned w1f[4][4][2];
    #pragma unroll
    for (int ks = 0; ks < 4; ks++)
        #pragma unroll
        for (int nt = 0; nt < 4; nt++) {
            const float* base = Wa1 + (16 * ks + 2 * c) * HID + 8 * nt + r;
            w1f[ks][nt][0] = pack_bf16(base[0],        base[HID]);
            w1f[ks][nt][1] = pack_bf16(base[8 * HID],  base[9 * HID]);
        }
    unsigned w2f[2][2];
    #pragma unroll
    for (int ks = 0; ks < 2; ks++) {
        const float* base = Wa2 + (16 * ks + 2 * c) * HH + r;
        w2f[ks][0] = pack_bf16(base[0],      base[HH]);
        w2f[ks][1] = pack_bf16(base[8 * HH], base[9 * HH]);
    }
    float bb0[4], bb1[4];
    #pragma unroll
    for (int nt = 0; nt < 4; nt++) {
        bb0[nt] = ba1[8 * nt + 2 * c];
        bb1[nt] = ba1[8 * nt + 2 * c + 1];
    }
    const float b2r0 = ba2[2 * c], b2r1 = ba2[2 * c + 1];

    #pragma unroll
    for (int e = 0; e < 32; e++) {
        int row = blockbase + 32 * warp + e;
        float2 v = (row < NN) ? *(const float2*)(h + (size_t)row * FF + 2 * lane)
                              : make_float2(0.0f, 0.0f);
        unsigned hv, lv;
        split_pack(v.x, v.y, hv, lv);
        AHI[(32 * warp + e) * LMW32 + lane] = hv;
        ALO[(32 * warp + e) * LMW32 + lane] = lv;
    }
    __syncthreads();

    float* gout = mat ? g_dst_buf : g_src_buf;
    unsigned* gbf = mat ? g_dst_bf : g_src_bf;
    #pragma unroll
    for (int mt = 0; mt < 8; mt++) {
        float acc[4][4];
        #pragma unroll
        for (int nt = 0; nt < 4; nt++)
            acc[nt][0] = acc[nt][1] = acc[nt][2] = acc[nt][3] = 0.0f;

        #pragma unroll
        for (int ks = 0; ks < 4; ks++) {
            int base = (mt * 16 + r) * LMW32 + 8 * ks + c;
            unsigned ah[4], al[4];
            ah[0] = AHI[base];                 al[0] = ALO[base];
            ah[1] = AHI[base + 8 * LMW32];     al[1] = ALO[base + 8 * LMW32];
            ah[2] = AHI[base + 4];             al[2] = ALO[base + 4];
            ah[3] = AHI[base + 8 * LMW32 + 4]; al[3] = ALO[base + 8 * LMW32 + 4];
            #pragma unroll
            for (int nt = 0; nt < 4; nt++) {
                mma16816(acc[nt], ah, blo[ks][nt]);
                mma16816(acc[nt], al, bhi[ks][nt]);
                mma16816(acc[nt], ah, bhi[ks][nt]);
            }
        }

        int row0 = blockbase + 16 * mt + r;
        int row8 = row0 + 8;
        #pragma unroll
        for (int nt = 0; nt < 4; nt++) {
            int col = colbase + 8 * nt + 2 * c;
            if (row0 < NN) {
                float v0 = acc[nt][0] + gb0[nt], v1 = acc[nt][1] + gb1[nt];
                *(float2*)(gout + (size_t)row0 * FF + col) = make_float2(v0, v1);
                gbf[(size_t)row0 * (FF / 2) + (col >> 1)] = pack_bf16(v0, v1);
            }
            if (row8 < NN) {
                float v0 = acc[nt][2] + gb0[nt], v1 = acc[nt][3] + gb1[nt];
                *(float2*)(gout + (size_t)row8 * FF + col) = make_float2(v0, v1);
                gbf[(size_t)row8 * (FF / 2) + (col >> 1)] = pack_bf16(v0, v1);
            }
        }
    }
    __syncthreads();

    const int nbase = blockbase + 32 * warp;
    if (nbase >= NN) return;

    unsigned* lmW = &AHI[(32 * warp) * LMW32];
    float* attW = &ATT[warp][0];
    const int myh = lane >> 2;

    #pragma unroll
    for (int e = 0; e < 32; e++) {
        float2 dv = *(const float2*)(g_dst_buf + (size_t)(nbase + e) * FF + 2 * lane);
        lmW[e * LMW32 + lane] = pack_bf16(leaky(dv.x), leaky(dv.y));
    }
    __syncwarp();

    #pragma unroll
    for (int mt = 0; mt < 2; mt++) {
        float acc[4][4];
        #pragma unroll
        for (int nt = 0; nt < 4; nt++)
            acc[nt][0] = acc[nt][1] = acc[nt][2] = acc[nt][3] = 0.0f;

        #pragma unroll
        for (int ks = 0; ks < 4; ks++) {
            unsigned a[4];
            int base = (mt * 16 + r) * LMW32 + 8 * ks + c;
            a[0] = lmW[base];
            a[1] = lmW[base + 8 * LMW32];
            a[2] = lmW[base + 4];
            a[3] = lmW[base + 8 * LMW32 + 4];
            #pragma unroll
            for (int nt = 0; nt < 4; nt++)
                mma16816(acc[nt], a, w1f[ks][nt]);
        }

        unsigned a2[2][4];
        #pragma unroll
        for (int nt = 0; nt < 4; nt++) {
            float v0 = leaky(acc[nt][0] + bb0[nt]);
            float v1 = leaky(acc[nt][1] + bb1[nt]);
            float v2 = leaky(acc[nt][2] + bb0[nt]);
            float v3 = leaky(acc[nt][3] + bb1[nt]);
            a2[nt >> 1][(nt & 1) * 2 + 0] = pack_bf16(v0, v1);
            a2[nt >> 1][(nt & 1) * 2 + 1] = pack_bf16(v2, v3);
        }

        float z[4] = {0.0f, 0.0f, 0.0f, 0.0f};
        mma16816(z, a2[0], w2f[0]);
        mma16816(z, a2[1], w2f[1]);

        *(float2*)&attW[(mt * 16 + r) * ATTS + 2 * c] =
            make_float2(sigm(z[0] + b2r0), sigm(z[1] + b2r1));
        *(float2*)&attW[(mt * 16 + r + 8) * ATTS + 2 * c] =
            make_float2(sigm(z[2] + b2r0), sigm(z[3] + b2r1));
    }
    __syncwarp();

    #pragma unroll
    for (int e = 0; e < 32; e++) {
        float av = attW[e * ATTS + myh];
        float2 dv = *(const float2*)(g_dst_buf + (size_t)(nbase + e) * FF + 2 * lane);
        *(float2*)(out + (size_t)(nbase + e) * FF + 2 * lane) =
            make_float2(av * dv.x, av * dv.y);
    }
}

// ---------------------------------------------------------------------------
// E1: edge attention (unchanged from round 10). Double-buffered gather +
// MMA MLP; att -> global fp32.
__global__ __launch_bounds__(128) void edge_att_kernel(
    const void* __restrict__ edge_index,
    const float* __restrict__ Wa1, const float* __restrict__ ba1,
    const float* __restrict__ Wa2, const float* __restrict__ ba2)
{
    __shared__ unsigned LM[4][2][32 * LMW32];

    const int tid  = threadIdx.x;
    const int warp = tid >> 5;
    const int lane = tid & 31;
    const int c = lane & 3;
    const int r = lane >> 2;
    const int half = lane >> 4;
    const int sub  = lane & 15;

    unsigned w1f[4][4][2];
    #pragma unroll
    for (int ks = 0; ks < 4; ks++)
        #pragma unroll
        for (int nt = 0; nt < 4; nt++) {
            const float* base = Wa1 + (16 * ks + 2 * c) * HID + 8 * nt + r;
            w1f[ks][nt][0] = pack_bf16(base[0],        base[HID]);
            w1f[ks][nt][1] = pack_bf16(base[8 * HID],  base[9 * HID]);
        }
    unsigned w2f[2][2];
    #pragma unroll
    for (int ks = 0; ks < 2; ks++) {
        const float* base = Wa2 + (16 * ks + 2 * c) * HH + r;
        w2f[ks][0] = pack_bf16(base[0],      base[HH]);
        w2f[ks][1] = pack_bf16(base[8 * HH], base[9 * HH]);
    }
    float bb0[4], bb1[4];
    #pragma unroll
    for (int nt = 0; nt < 4; nt++) {
        bb0[nt] = ba1[8 * nt + 2 * c];
        bb1[nt] = ba1[8 * nt + 2 * c + 1];
    }
    const float b2r0 = ba2[2 * c], b2r1 = ba2[2 * c + 1];

    const int is64 = g_idx_is64;
    const int wbase = (blockIdx.x * 4 + warp) * 5;

    auto load_idx = [&](int b, int& sI, int& dI) {
        const int ebase = (wbase + b) * 32;
        if (is64) {
            const long long* ei = (const long long*)edge_index;
            sI = (int)ei[ebase + lane];
            dI = (int)ei[EE + ebase + lane];
        } else {
            const int* ei = (const int*)edge_index;
            sI = ei[ebase + lane];
            dI = ei[EE + ebase + lane];
        }
    };

    auto gather = [&](int srcR, int dstR, unsigned* lmB) {
        #pragma unroll
        for (int i = 0; i < 16; i++) {
            int e = 2 * i + half;
            int s = __shfl_sync(0xffffffffu, srcR, e);
            int d = __shfl_sync(0xffffffffu, dstR, e);
            uint2 sv = *(const uint2*)(g_src_bf + (size_t)s * (FF / 2) + 2 * sub);
            uint2 dv = *(const uint2*)(g_dst_bf + (size_t)d * (FF / 2) + 2 * sub);
            float2 sa = unpack_bf16(sv.x), sb = unpack_bf16(sv.y);
            float2 da = unpack_bf16(dv.x), db = unpack_bf16(dv.y);
            unsigned p0 = pack_bf16(leaky(sa.x + da.x), leaky(sa.y + da.y));
            unsigned p1 = pack_bf16(leaky(sb.x + db.x), leaky(sb.y + db.y));
            *(uint2*)&lmB[e * LMW32 + 2 * sub] = make_uint2(p0, p1);
        }
    };

    int srcA, dstA;
    load_idx(0, srcA, dstA);
    gather(srcA, dstA, &LM[warp][0][0]);
    __syncwarp();

    for (int b = 0; b < 5; b++) {
        if (b < 4) {
            int srcN, dstN;
            load_idx(b + 1, srcN, dstN);
            gather(srcN, dstN, &LM[warp][(b + 1) & 1][0]);
        }

        unsigned* lmW = &LM[warp][b & 1][0];
        const int ebase = (wbase + b) * 32;
        #pragma unroll
        for (int mt = 0; mt < 2; mt++) {
            float acc[4][4];
            #pragma unroll
            for (int nt = 0; nt < 4; nt++)
                acc[nt][0] = acc[nt][1] = acc[nt][2] = acc[nt][3] = 0.0f;

            #pragma unroll
            for (int ks = 0; ks < 4; ks++) {
                unsigned a[4];
                int base = (mt * 16 + r) * LMW32 + 8 * ks + c;
                a[0] = lmW[base];
                a[1] = lmW[base + 8 * LMW32];
                a[2] = lmW[base + 4];
                a[3] = lmW[base + 8 * LMW32 + 4];
                #pragma unroll
                for (int nt = 0; nt < 4; nt++)
                    mma16816(acc[nt], a, w1f[ks][nt]);
            }

            unsigned a2[2][4];
            #pragma unroll
            for (int nt = 0; nt < 4; nt++) {
                float v0 = leaky(acc[nt][0] + bb0[nt]);
                float v1 = leaky(acc[nt][1] + bb1[nt]);
                float v2 = leaky(acc[nt][2] + bb0[nt]);
                float v3 = leaky(acc[nt][3] + bb1[nt]);
                a2[nt >> 1][(nt & 1) * 2 + 0] = pack_bf16(v0, v1);
                a2[nt >> 1][(nt & 1) * 2 + 1] = pack_bf16(v2, v3);
            }

            float z[4] = {0.0f, 0.0f, 0.0f, 0.0f};
            mma16816(z, a2[0], w2f[0]);
            mma16816(z, a2[1], w2f[1]);

            *(float2*)&att_buf[(size_t)(ebase + mt * 16 + r) * HH + 2 * c] =
                make_float2(sigm(z[0] + b2r0), sigm(z[1] + b2r1));
            *(float2*)&att_buf[(size_t)(ebase + mt * 16 + r + 8) * HH + 2 * c] =
                make_float2(sigm(z[2] + b2r0), sigm(z[3] + b2r1));
        }
        __syncwarp();
    }
}

// ---------------------------------------------------------------------------
// Pull kernel: out[n] += sum over CSR edges (att[eid] * g_src[src]).
// Half-warp per node, register accumulation, ONE plain RMW store. No atomics.
__global__ __launch_bounds__(128) void pull_kernel(float* __restrict__ out)
{
    const int tid = threadIdx.x;
    const int hw  = tid >> 4;        // 0..7: node within block
    const int sub = tid & 15;        // 16B chunk within row
    const int myh = sub >> 1;        // head for floats [4sub, 4sub+3]
    const int n = blockIdx.x * 8 + hw;   // NN = 12500 * 8 exactly

    const int k1 = off_buf[n + 1];
    int k = off_buf[n];

    float4 acc = make_float4(0.0f, 0.0f, 0.0f, 0.0f);

    // 2-way ILP over the edge list
    for (; k + 1 < k1; k += 2) {
        int2 ra = rec_buf[k];
        int2 rb = rec_buf[k + 1];
        float aa = att_buf[(size_t)ra.y * HH + myh];
        float ab = att_buf[(size_t)rb.y * HH + myh];
        float4 sa = *(const float4*)(g_src_buf + (size_t)ra.x * FF + 4 * sub);
        float4 sb = *(const float4*)(g_src_buf + (size_t)rb.x * FF + 4 * sub);
        acc.x += aa * sa.x + ab * sb.x;
        acc.y += aa * sa.y + ab * sb.y;
        acc.z += aa * sa.z + ab * sb.z;
        acc.w += aa * sa.w + ab * sb.w;
    }
    if (k < k1) {
        int2 ra = rec_buf[k];
        float aa = att_buf[(size_t)ra.y * HH + myh];
        float4 sa = *(const float4*)(g_src_buf + (size_t)ra.x * FF + 4 * sub);
        acc.x += aa * sa.x;
        acc.y += aa * sa.y;
        acc.z += aa * sa.z;
        acc.w += aa * sa.w;
    }

    float4* op = (float4*)(out + (size_t)n * FF + 4 * sub);
    float4 cv = *op;
    cv.x += acc.x; cv.y += acc.y; cv.z += acc.z; cv.w += acc.w;
    *op = cv;
}

// ---------------------------------------------------------------------------
extern "C" void kernel_launch(void* const* d_in, const int* in_sizes, int n_in,
                              void* d_out, int out_size)
{
    const float* h      = (const float*)d_in[0];
    const float* W_src  = (const float*)d_in[1];
    const float* b_src  = (const float*)d_in[2];
    const float* W_dst  = (const float*)d_in[3];
    const float* b_dst  = (const float*)d_in[4];
    const float* Wa1_s  = (const float*)d_in[5];
    const float* ba1_s  = (const float*)d_in[6];
    const float* Wa2_s  = (const float*)d_in[7];
    const float* ba2_s  = (const float*)d_in[8];
    const float* Wa1_d  = (const float*)d_in[9];
    const float* ba1_d  = (const float*)d_in[10];
    const float* Wa2_d  = (const float*)d_in[11];
    const float* ba2_d  = (const float*)d_in[12];
    const void*  eidx   = (const void*)d_in[13];
    float* out = (float*)d_out;

    // CSR build (independent of node kernel)
    zero_kernel<<<(NN + 255) / 256, 256>>>((const unsigned int*)eidx);
    hist_kernel<<<(EE + 255) / 256, 256>>>(eidx);
    scan_kernel<<<1, 1024>>>();
    fill_kernel<<<(EE + 255) / 256, 256>>>(eidx);

    // node GEMM + node attention (writes out base term)
    node_kernel<<<(NN + 127) / 128, 128>>>(
        h, W_src, b_src, W_dst, b_dst,
        Wa1_d, ba1_d, Wa2_d, ba2_d, out);

    // per-edge attention
    edge_att_kernel<<<EE / (4 * 5 * 32), 128>>>(
        eidx, Wa1_s, ba1_s, Wa2_s, ba2_s);

    // pull aggregation (no atomics)
    pull_kernel<<<NN / 8, 128>>>(out);
}

// round 13
// speedup vs baseline: 1.9342x; 1.9342x over previous
#include <cuda_runtime.h>
#include <cuda_bf16.h>

#define NN 100000
#define FF 64
#define HH 8
#define DD 8
#define EE 1200000
#define HID 32

// scratch (allocation-free rule: __device__ globals)
__device__ float g_src_buf[NN * FF];
__device__ float g_dst_buf[NN * FF];
__device__ int g_idx_is64;

__device__ __forceinline__ float leaky(float x) { return fmaxf(x, 0.2f * x); }
__device__ __forceinline__ float sigm(float x) { return 1.0f / (1.0f + __expf(-x)); }

__device__ __forceinline__ void red4(float* p, float x, float y, float z, float w) {
    asm volatile("red.global.add.v4.f32 [%0], {%1,%2,%3,%4};"
                 :: "l"(p), "f"(x), "f"(y), "f"(z), "f"(w) : "memory");
}

__device__ __forceinline__ unsigned pack_bf16(float lo, float hi) {
    __nv_bfloat162 t = __float22bfloat162_rn(make_float2(lo, hi));
    return *(unsigned*)&t;
}

// split x into bf16 hi + bf16 lo (residual)
__device__ __forceinline__ void split_pack(float a, float b, unsigned& hi, unsigned& lo) {
    __nv_bfloat16 ah = __float2bfloat16(a), bh = __float2bfloat16(b);
    float ar = a - __bfloat162float(ah);
    float br = b - __bfloat162float(bh);
    __nv_bfloat162 t; t.x = ah; t.y = bh;
    hi = *(unsigned*)&t;
    lo = pack_bf16(ar, br);
}

// D += A@B, m16n8k16, bf16 in / fp32 accum
__device__ __forceinline__ void mma16816(float* d, const unsigned* a, const unsigned* b) {
    asm volatile(
        "mma.sync.aligned.m16n8k16.row.col.f32.bf16.bf16.f32 "
        "{%0,%1,%2,%3}, {%4,%5,%6,%7}, {%8,%9}, {%0,%1,%2,%3};"
        : "+f"(d[0]), "+f"(d[1]), "+f"(d[2]), "+f"(d[3])
        : "r"(a[0]), "r"(a[1]), "r"(a[2]), "r"(a[3]), "r"(b[0]), "r"(b[1]));
}

#define LMW32 36               // staging row stride in uint32 (72 bf16), conflict-free
#define ATTS 10                // att row stride

// ---------------------------------------------------------------------------
// Fused node kernel (R8 version, no bf16 mirrors): tensor-core GEMM
// (hi/lo split) + node attention.
__global__ __launch_bounds__(128) void node_kernel(
    const float* __restrict__ h,
    const float* __restrict__ W_src, const float* __restrict__ b_src,
    const float* __restrict__ W_dst, const float* __restrict__ b_dst,
    const float* __restrict__ Wa1, const float* __restrict__ ba1,
    const float* __restrict__ Wa2, const float* __restrict__ ba2,
    const unsigned int* __restrict__ eidx_words,
    float* __restrict__ out)
{
    __shared__ unsigned AHI[128 * LMW32];
    __shared__ unsigned ALO[128 * LMW32];
    __shared__ float ATT[4][32 * ATTS];

    const int tid  = threadIdx.x;
    const int warp = tid >> 5;
    const int lane = tid & 31;
    const int c = lane & 3;
    const int r = lane >> 2;
    const int blockbase = blockIdx.x * 128;

    if (blockIdx.x == 0 && tid == 0) {
        int is64 = 1;
        for (int i = 0; i < 8; i++)
            if (eidx_words[2 * i + 1] != 0u) is64 = 0;
        g_idx_is64 = is64;
    }

    const int mat = warp >> 1;
    const int colbase = 32 * (warp & 1);
    const float* Wm = mat ? W_dst : W_src;
    const float* bm = mat ? b_dst : b_src;

    unsigned bhi[4][4][2], blo[4][4][2];
    #pragma unroll
    for (int ks = 0; ks < 4; ks++)
        #pragma unroll
        for (int nt = 0; nt < 4; nt++) {
            const float* base = Wm + (16 * ks + 2 * c) * FF + colbase + 8 * nt + r;
            split_pack(base[0],       base[FF],     bhi[ks][nt][0], blo[ks][nt][0]);
            split_pack(base[8 * FF],  base[9 * FF], bhi[ks][nt][1], blo[ks][nt][1]);
        }
    float gb0[4], gb1[4];
    #pragma unroll
    for (int nt = 0; nt < 4; nt++) {
        gb0[nt] = bm[colbase + 8 * nt + 2 * c];
        gb1[nt] = bm[colbase + 8 * nt + 2 * c + 1];
    }

    unsigned w1f[4][4][2];
    #pragma unroll
    for (int ks = 0; ks < 4; ks++)
        #pragma unroll
        for (int nt = 0; nt < 4; nt++) {
            const float* base = Wa1 + (16 * ks + 2 * c) * HID + 8 * nt + r;
            w1f[ks][nt][0] = pack_bf16(base[0],        base[HID]);
            w1f[ks][nt][1] = pack_bf16(base[8 * HID],  base[9 * HID]);
        }
    unsigned w2f[2][2];
    #pragma unroll
    for (int ks = 0; ks < 2; ks++) {
        const float* base = Wa2 + (16 * ks + 2 * c) * HH + r;
        w2f[ks][0] = pack_bf16(base[0],      base[HH]);
        w2f[ks][1] = pack_bf16(base[8 * HH], base[9 * HH]);
    }
    float bb0[4], bb1[4];
    #pragma unroll
    for (int nt = 0; nt < 4; nt++) {
        bb0[nt] = ba1[8 * nt + 2 * c];
        bb1[nt] = ba1[8 * nt + 2 * c + 1];
    }
    const float b2r0 = ba2[2 * c], b2r1 = ba2[2 * c + 1];

    #pragma unroll
    for (int e = 0; e < 32; e++) {
        int row = blockbase + 32 * warp + e;
        float2 v = (row < NN) ? *(const float2*)(h + (size_t)row * FF + 2 * lane)
                              : make_float2(0.0f, 0.0f);
        unsigned hv, lv;
        split_pack(v.x, v.y, hv, lv);
        AHI[(32 * warp + e) * LMW32 + lane] = hv;
        ALO[(32 * warp + e) * LMW32 + lane] = lv;
    }
    __syncthreads();

    float* gout = mat ? g_dst_buf : g_src_buf;
    #pragma unroll
    for (int mt = 0; mt < 8; mt++) {
        float acc[4][4];
        #pragma unroll
        for (int nt = 0; nt < 4; nt++)
            acc[nt][0] = acc[nt][1] = acc[nt][2] = acc[nt][3] = 0.0f;

        #pragma unroll
        for (int ks = 0; ks < 4; ks++) {
            int base = (mt * 16 + r) * LMW32 + 8 * ks + c;
            unsigned ah[4], al[4];
            ah[0] = AHI[base];                 al[0] = ALO[base];
            ah[1] = AHI[base + 8 * LMW32];     al[1] = ALO[base + 8 * LMW32];
            ah[2] = AHI[base + 4];             al[2] = ALO[base + 4];
            ah[3] = AHI[base + 8 * LMW32 + 4]; al[3] = ALO[base + 8 * LMW32 + 4];
            #pragma unroll
            for (int nt = 0; nt < 4; nt++) {
                mma16816(acc[nt], ah, blo[ks][nt]);
                mma16816(acc[nt], al, bhi[ks][nt]);
                mma16816(acc[nt], ah, bhi[ks][nt]);
            }
        }

        int row0 = blockbase + 16 * mt + r;
        int row8 = row0 + 8;
        #pragma unroll
        for (int nt = 0; nt < 4; nt++) {
            int col = colbase + 8 * nt + 2 * c;
            if (row0 < NN)
                *(float2*)(gout + (size_t)row0 * FF + col) =
                    make_float2(acc[nt][0] + gb0[nt], acc[nt][1] + gb1[nt]);
            if (row8 < NN)
                *(float2*)(gout + (size_t)row8 * FF + col) =
                    make_float2(acc[nt][2] + gb0[nt], acc[nt][3] + gb1[nt]);
        }
    }
    __syncthreads();

    const int nbase = blockbase + 32 * warp;
    if (nbase >= NN) return;

    unsigned* lmW = &AHI[(32 * warp) * LMW32];
    float* attW = &ATT[warp][0];
    const int myh = lane >> 2;

    #pragma unroll
    for (int e = 0; e < 32; e++) {
        float2 dv = *(const float2*)(g_dst_buf + (size_t)(nbase + e) * FF + 2 * lane);
        lmW[e * LMW32 + lane] = pack_bf16(leaky(dv.x), leaky(dv.y));
    }
    __syncwarp();

    #pragma unroll
    for (int mt = 0; mt < 2; mt++) {
        float acc[4][4];
        #pragma unroll
        for (int nt = 0; nt < 4; nt++)
            acc[nt][0] = acc[nt][1] = acc[nt][2] = acc[nt][3] = 0.0f;

        #pragma unroll
        for (int ks = 0; ks < 4; ks++) {
            unsigned a[4];
            int base = (mt * 16 + r) * LMW32 + 8 * ks + c;
            a[0] = lmW[base];
            a[1] = lmW[base + 8 * LMW32];
            a[2] = lmW[base + 4];
            a[3] = lmW[base + 8 * LMW32 + 4];
            #pragma unroll
            for (int nt = 0; nt < 4; nt++)
                mma16816(acc[nt], a, w1f[ks][nt]);
        }

        unsigned a2[2][4];
        #pragma unroll
        for (int nt = 0; nt < 4; nt++) {
            float v0 = leaky(acc[nt][0] + bb0[nt]);
            float v1 = leaky(acc[nt][1] + bb1[nt]);
            float v2 = leaky(acc[nt][2] + bb0[nt]);
            float v3 = leaky(acc[nt][3] + bb1[nt]);
            a2[nt >> 1][(nt & 1) * 2 + 0] = pack_bf16(v0, v1);
            a2[nt >> 1][(nt & 1) * 2 + 1] = pack_bf16(v2, v3);
        }

        float z[4] = {0.0f, 0.0f, 0.0f, 0.0f};
        mma16816(z, a2[0], w2f[0]);
        mma16816(z, a2[1], w2f[1]);

        *(float2*)&attW[(mt * 16 + r) * ATTS + 2 * c] =
            make_float2(sigm(z[0] + b2r0), sigm(z[1] + b2r1));
        *(float2*)&attW[(mt * 16 + r + 8) * ATTS + 2 * c] =
            make_float2(sigm(z[2] + b2r0), sigm(z[3] + b2r1));
    }
    __syncwarp();

    #pragma unroll
    for (int e = 0; e < 32; e++) {
        float av = attW[e * ATTS + myh];
        float2 dv = *(const float2*)(g_dst_buf + (size_t)(nbase + e) * FF + 2 * lane);
        *(float2*)(out + (size_t)(nbase + e) * FF + 2 * lane) =
            make_float2(av * dv.x, av * dv.y);
    }
}

// ---------------------------------------------------------------------------
// Edge kernel v6: R8 fused structure (fp32 gather, red4 scatter) with
// double-buffered LM so gather(b+1) is issued BEFORE MMA(b) — gather L2
// latency hides under tensor work instead of serializing.
__global__ __launch_bounds__(128) void edge_kernel(
    const void* __restrict__ edge_index,
    const float* __restrict__ Wa1, const float* __restrict__ ba1,
    const float* __restrict__ Wa2, const float* __restrict__ ba2,
    float* __restrict__ out)
{
    __shared__ unsigned LM[4][2][32 * LMW32];   // double-buffered per warp
    __shared__ float ATT[4][32 * ATTS];

    const int tid  = threadIdx.x;
    const int warp = tid >> 5;
    const int lane = tid & 31;
    const int c = lane & 3;
    const int r = lane >> 2;
    const int half = lane >> 4;      // which edge of the pair
    const int sub  = lane & 15;      // 16B chunk within row
    const int myh4 = sub >> 1;       // head for floats [4sub, 4sub+3]

    unsigned w1f[4][4][2];
    #pragma unroll
    for (int ks = 0; ks < 4; ks++)
        #pragma unroll
        for (int nt = 0; nt < 4; nt++) {
            const float* base = Wa1 + (16 * ks + 2 * c) * HID + 8 * nt + r;
            w1f[ks][nt][0] = pack_bf16(base[0],        base[HID]);
            w1f[ks][nt][1] = pack_bf16(base[8 * HID],  base[9 * HID]);
        }
    unsigned w2f[2][2];
    #pragma unroll
    for (int ks = 0; ks < 2; ks++) {
        const float* base = Wa2 + (16 * ks + 2 * c) * HH + r;
        w2f[ks][0] = pack_bf16(base[0],      base[HH]);
        w2f[ks][1] = pack_bf16(base[8 * HH], base[9 * HH]);
    }
    float bb0[4], bb1[4];
    #pragma unroll
    for (int nt = 0; nt < 4; nt++) {
        bb0[nt] = ba1[8 * nt + 2 * c];
        bb1[nt] = ba1[8 * nt + 2 * c + 1];
    }
    const float b2r0 = ba2[2 * c], b2r1 = ba2[2 * c + 1];

    float* attW = &ATT[warp][0];
    const int is64 = g_idx_is64;
    const int wbase = (blockIdx.x * 4 + warp) * 5;

    auto load_idx = [&](int b, int& sI, int& dI) {
        const int ebase = (wbase + b) * 32;
        if (is64) {
            const long long* ei = (const long long*)edge_index;
            sI = (int)ei[ebase + lane];
            dI = (int)ei[EE + ebase + lane];
        } else {
            const int* ei = (const int*)edge_index;
            sI = ei[ebase + lane];
            dI = ei[EE + ebase + lane];
        }
    };

    // gather a full batch (fp32 rows) into LM buffer
    auto gather = [&](int srcR, int dstR, unsigned* lmB) {
        #pragma unroll
        for (int i = 0; i < 16; i++) {
            int e = 2 * i + half;
            int s = __shfl_sync(0xffffffffu, srcR, e);
            int d = __shfl_sync(0xffffffffu, dstR, e);
            float4 sv = *(const float4*)(g_src_buf + (size_t)s * FF + 4 * sub);
            float4 dv = *(const float4*)(g_dst_buf + (size_t)d * FF + 4 * sub);
            unsigned p0 = pack_bf16(leaky(sv.x + dv.x), leaky(sv.y + dv.y));
            unsigned p1 = pack_bf16(leaky(sv.z + dv.z), leaky(sv.w + dv.w));
            *(uint2*)&lmB[e * LMW32 + 2 * sub] = make_uint2(p0, p1);
        }
    };

    int srcA, dstA;                  // indices for current batch
    load_idx(0, srcA, dstA);
    gather(srcA, dstA, &LM[warp][0][0]);

    int srcN, dstN;                  // indices for next batch

    for (int b = 0; b < 5; b++) {
        // issue next batch's gather FIRST (latency hides under MMA below)
        const bool more = (b < 4);
        if (more) {
            load_idx(b + 1, srcN, dstN);
            gather(srcN, dstN, &LM[warp][(b + 1) & 1][0]);
        }
        __syncwarp();   // LM[b&1] (written last iteration / prologue) visible

        // ---- MMA MLP on batch b ----
        unsigned* lmW = &LM[warp][b & 1][0];
        #pragma unroll
        for (int mt = 0; mt < 2; mt++) {
            float acc[4][4];
            #pragma unroll
            for (int nt = 0; nt < 4; nt++)
                acc[nt][0] = acc[nt][1] = acc[nt][2] = acc[nt][3] = 0.0f;

            #pragma unroll
            for (int ks = 0; ks < 4; ks++) {
                unsigned a[4];
                int base = (mt * 16 + r) * LMW32 + 8 * ks + c;
                a[0] = lmW[base];
                a[1] = lmW[base + 8 * LMW32];
                a[2] = lmW[base + 4];
                a[3] = lmW[base + 8 * LMW32 + 4];
                #pragma unroll
                for (int nt = 0; nt < 4; nt++)
                    mma16816(acc[nt], a, w1f[ks][nt]);
            }

            unsigned a2[2][4];
            #pragma unroll
            for (int nt = 0; nt < 4; nt++) {
                float v0 = leaky(acc[nt][0] + bb0[nt]);
                float v1 = leaky(acc[nt][1] + bb1[nt]);
                float v2 = leaky(acc[nt][2] + bb0[nt]);
                float v3 = leaky(acc[nt][3] + bb1[nt]);
                a2[nt >> 1][(nt & 1) * 2 + 0] = pack_bf16(v0, v1);
                a2[nt >> 1][(nt & 1) * 2 + 1] = pack_bf16(v2, v3);
            }

            float z[4] = {0.0f, 0.0f, 0.0f, 0.0f};
            mma16816(z, a2[0], w2f[0]);
            mma16816(z, a2[1], w2f[1]);

            *(float2*)&attW[(mt * 16 + r) * ATTS + 2 * c] =
                make_float2(sigm(z[0] + b2r0), sigm(z[1] + b2r1));
            *(float2*)&attW[(mt * 16 + r + 8) * ATTS + 2 * c] =
                make_float2(sigm(z[2] + b2r0), sigm(z[3] + b2r1));
        }
        __syncwarp();

        // ---- scatter batch b (src rows L1-hot from gather) ----
        #pragma unroll
        for (int i = 0; i < 16; i++) {
            int e = 2 * i + half;
            int s = __shfl_sync(0xffffffffu, srcA, e);
            int d = __shfl_sync(0xffffffffu, dstA, e);
            float av = attW[e * ATTS + myh4];
            float4 sv = *(const float4*)(g_src_buf + (size_t)s * FF + 4 * sub);
            red4(out + (size_t)d * FF + 4 * sub,
                 av * sv.x, av * sv.y, av * sv.z, av * sv.w);
        }
        srcA = srcN; dstA = dstN;
    }
}

// ---------------------------------------------------------------------------
extern "C" void kernel_launch(void* const* d_in, const int* in_sizes, int n_in,
                              void* d_out, int out_size)
{
    const float* h      = (const float*)d_in[0];
    const float* W_src  = (const float*)d_in[1];
    const float* b_src  = (const float*)d_in[2];
    const float* W_dst  = (const float*)d_in[3];
    const float* b_dst  = (const float*)d_in[4];
    const float* Wa1_s  = (const float*)d_in[5];
    const float* ba1_s  = (const float*)d_in[6];
    const float* Wa2_s  = (const float*)d_in[7];
    const float* ba2_s  = (const float*)d_in[8];
    const float* Wa1_d  = (const float*)d_in[9];
    const float* ba1_d  = (const float*)d_in[10];
    const float* Wa2_d  = (const float*)d_in[11];
    const float* ba2_d  = (const float*)d_in[12];
    const void*  eidx   = (const void*)d_in[13];
    float* out = (float*)d_out;

    node_kernel<<<(NN + 127) / 128, 128>>>(
        h, W_src, b_src, W_dst, b_dst,
        Wa1_d, ba1_d, Wa2_d, ba2_d,
        (const unsigned int*)eidx, out);

    edge_kernel<<<EE / (4 * 5 * 32), 128>>>(
        eidx, Wa1_s, ba1_s, Wa2_s, ba2_s, out);
}